// round 2
// baseline (speedup 1.0000x reference)
#include <cuda_runtime.h>
#include <math.h>

// Shapes (fixed):
//   x:       (1024, 1, 63, 250) fp32   -> nodes (63, 256000), k = a*250 + d
//   W:       (256000, 256) fp32
//   att_src, att_dst, bias: (256,) fp32
//   out:     (63, 1) fp32
#define NA    1024
#define NC    63
#define ND    250
#define NOUT  256

// ---- scratch (no allocations allowed) ----
// partial[t*63 + c][a], t in {0:a_src, 1:a_dst, 2:hbar}
__device__ float g_partial[3 * NC * NA];
__device__ float g_out3[3 * NC];
__device__ float g_bm;
__device__ int   g_ctr = 0;

// ============================================================================
// Kernel 1: fused W-projection + x contraction. One block per batch index a.
//   Phase 1: project this block's 250 contiguous W rows onto
//            {att_src, att_dst, ones/256} -> smem v[250][3].  (streams 256KB W)
//   Phase 2: dot each of the 63 node rows x[a,0,c,:] with v.   (streams 63KB x)
// All 1024 blocks resident in one wave (8 blocks/SM). Pure HBM stream.
// ============================================================================
__global__ void __launch_bounds__(256) fused_main_kernel(
    const float* __restrict__ x,
    const float* __restrict__ W,
    const float* __restrict__ att_src,
    const float* __restrict__ att_dst)
{
    __shared__ float s0[ND], s1[ND], s2[ND];

    const int a    = blockIdx.x;
    const int warp = threadIdx.x >> 5;
    const int lane = threadIdx.x & 31;

    // Per-lane attention slices (cols lane*4..+4 and 128+lane*4..+4), loaded once.
    const float4* __restrict__ s4 = reinterpret_cast<const float4*>(att_src);
    const float4* __restrict__ d4 = reinterpret_cast<const float4*>(att_dst);
    const float4 a0 = s4[lane], a1 = s4[lane + 32];
    const float4 b0 = d4[lane], b1 = d4[lane + 32];

    // ---- Phase 1: W rows k = a*250 + d, d = warp, warp+8, ... ----
    const float4* __restrict__ Wbase =
        reinterpret_cast<const float4*>(W) + (size_t)a * ND * (NOUT / 4);

    #pragma unroll 2
    for (int d = warp; d < ND; d += 8) {
        const float4* __restrict__ Wr = Wbase + (size_t)d * (NOUT / 4);
        const float4 w0 = Wr[lane];
        const float4 w1 = Wr[lane + 32];

        float ss = w0.x * a0.x + w0.y * a0.y + w0.z * a0.z + w0.w * a0.w
                 + w1.x * a1.x + w1.y * a1.y + w1.z * a1.z + w1.w * a1.w;
        float sd = w0.x * b0.x + w0.y * b0.y + w0.z * b0.z + w0.w * b0.w
                 + w1.x * b1.x + w1.y * b1.y + w1.z * b1.z + w1.w * b1.w;
        float sm = w0.x + w0.y + w0.z + w0.w + w1.x + w1.y + w1.z + w1.w;

        #pragma unroll
        for (int off = 16; off > 0; off >>= 1) {
            ss += __shfl_xor_sync(0xffffffffu, ss, off);
            sd += __shfl_xor_sync(0xffffffffu, sd, off);
            sm += __shfl_xor_sync(0xffffffffu, sm, off);
        }
        if (lane == 0) {
            s0[d] = ss;
            s1[d] = sd;
            s2[d] = sm * (1.0f / 256.0f);
        }
    }
    __syncthreads();

    // ---- Phase 2: 63 node rows, one warp each (round-robin) ----
    const float* __restrict__ xa = x + (size_t)a * (NC * ND);
    for (int c = warp; c < NC; c += 8) {
        const float* __restrict__ xr = xa + c * ND;
        float p0 = 0.f, p1 = 0.f, p2 = 0.f;
        #pragma unroll 4
        for (int d = lane; d < ND; d += 32) {
            const float xv = xr[d];
            p0 = fmaf(xv, s0[d], p0);
            p1 = fmaf(xv, s1[d], p1);
            p2 = fmaf(xv, s2[d], p2);
        }
        #pragma unroll
        for (int off = 16; off > 0; off >>= 1) {
            p0 += __shfl_xor_sync(0xffffffffu, p0, off);
            p1 += __shfl_xor_sync(0xffffffffu, p1, off);
            p2 += __shfl_xor_sync(0xffffffffu, p2, off);
        }
        if (lane == 0) {
            g_partial[(0 * NC + c) * NA + a] = p0;
            g_partial[(1 * NC + c) * NA + a] = p1;
            g_partial[(2 * NC + c) * NA + a] = p2;
        }
    }
}

// ============================================================================
// Kernel 2: reduce the 1024 batch-partials per slot (189 blocks) + bias mean
// (block 189). The last block to finish runs the 63x63 softmax in-kernel
// (reads via __ldcg for coherence) and resets the counter for graph replay.
// ============================================================================
__global__ void __launch_bounds__(256) finish_kernel(
    const float* __restrict__ bias, float* __restrict__ out)
{
    const int b   = blockIdx.x;     // 0..188 partial slots, 189 = bias
    const int tid = threadIdx.x;
    __shared__ float sh[256];

    if (b < 3 * NC) {
        const float* __restrict__ p = g_partial + b * NA;
        float s = p[tid] + p[tid + 256] + p[tid + 512] + p[tid + 768];
        sh[tid] = s;
        __syncthreads();
        #pragma unroll
        for (int st = 128; st > 0; st >>= 1) {
            if (tid < st) sh[tid] += sh[tid + st];
            __syncthreads();
        }
        if (tid == 0) g_out3[b] = sh[0];
    } else {
        sh[tid] = bias[tid];        // NOUT == 256 == blockDim
        __syncthreads();
        #pragma unroll
        for (int st = 128; st > 0; st >>= 1) {
            if (tid < st) sh[tid] += sh[tid + st];
            __syncthreads();
        }
        if (tid == 0) g_bm = sh[0] * (1.0f / 256.0f);
    }

    // ---- last-block softmax ----
    __threadfence();
    __shared__ int is_last;
    if (tid == 0) is_last = (atomicAdd(&g_ctr, 1) == 3 * NC);  // 190 blocks total
    __syncthreads();
    if (!is_last) return;

    __shared__ float as_[NC], ad_[NC], hb_[NC], bm_s;
    if (tid < NC)          as_[tid]       = __ldcg(&g_out3[0 * NC + tid]);
    else if (tid < 2 * NC) ad_[tid - NC]  = __ldcg(&g_out3[1 * NC + (tid - NC)]);
    else if (tid < 3 * NC) hb_[tid - 2*NC]= __ldcg(&g_out3[2 * NC + (tid - 2 * NC)]);
    if (tid == 0) bm_s = __ldcg(&g_bm);
    __syncthreads();

    if (tid < NC) {
        const float ai = ad_[tid];
        float m = -1e30f;
        #pragma unroll 7
        for (int j = 0; j < NC; j++) {
            float e = ai + as_[j];
            e = (e > 0.f) ? e : 0.2f * e;
            m = fmaxf(m, e);
        }
        float Z = 0.f, S = 0.f;
        #pragma unroll 7
        for (int j = 0; j < NC; j++) {
            float e = ai + as_[j];
            e = (e > 0.f) ? e : 0.2f * e;
            const float w = __expf(e - m);
            Z += w;
            S = fmaf(w, hb_[j], S);
        }
        out[tid] = S / Z + bm_s;
    }
    if (tid == 0) g_ctr = 0;   // reset for next graph replay
}

// ============================================================================
extern "C" void kernel_launch(void* const* d_in, const int* in_sizes, int n_in,
                              void* d_out, int out_size)
{
    const float* x       = (const float*)d_in[0];
    const float* W       = (const float*)d_in[1];
    const float* att_src = (const float*)d_in[2];
    const float* att_dst = (const float*)d_in[3];
    const float* bias    = (const float*)d_in[4];
    float* out = (float*)d_out;

    fused_main_kernel<<<NA, 256>>>(x, W, att_src, att_dst);
    finish_kernel<<<3 * NC + 1, 256>>>(bias, out);
}